// round 8
// baseline (speedup 1.0000x reference)
#include <cuda_runtime.h>
#include <cstdint>

#define BB 4
#define LQ 256
#define LK 256
#define DD 768

// Scratch (no cudaMalloc allowed)
__device__ float g_q[BB*LQ*DD];
__device__ float g_k[BB*LK*DD];
__device__ float g_v[BB*LK*DD];
__device__ float g_scores[BB*LQ*LK];

__device__ __forceinline__ float tanh_fast(float x) {
    float y;
    asm("tanh.approx.f32 %0, %1;" : "=f"(y) : "f"(x));
    return y;
}

// ---- tf32 helpers ----
__device__ __forceinline__ uint32_t f2tf32(float x) {
    uint32_t u;
    asm("cvt.rna.tf32.f32 %0, %1;" : "=r"(u) : "f"(x));
    return u;
}
__device__ __forceinline__ void mma_tf32(float& d0, float& d1, float& d2, float& d3,
                                         uint32_t a0, uint32_t a1, uint32_t a2, uint32_t a3,
                                         uint32_t b0, uint32_t b1) {
    asm("mma.sync.aligned.m16n8k8.row.col.f32.tf32.tf32.f32 "
        "{%0,%1,%2,%3}, {%4,%5,%6,%7}, {%8,%9}, {%0,%1,%2,%3};"
        : "+f"(d0), "+f"(d1), "+f"(d2), "+f"(d3)
        : "r"(a0), "r"(a1), "r"(a2), "r"(a3), "r"(b0), "r"(b1));
}

// ---------------------------------------------------------------------------
// Shared-memory layouts (union'd in the fused kernel)
// ---------------------------------------------------------------------------
struct ProjSmem {
    uint32_t As[2][64][36];     // [m][k] tf32
    uint32_t Bsm[2][32][136];   // [k][n] tf32
};
struct ScoreSmem {
    float Qs[32][65];
    float Ks[32][65];
    float Wss[64];
};

// ---------------------------------------------------------------------------
// One 64(M)x128(N) projection tile via tf32 mma. 256 thr (2Mx4N warps),
// BK=32 double-buffered.  Out[M,N] = X[M,K] @ W[K,N] + b[N], N=K=768.
// ---------------------------------------------------------------------------
__device__ __forceinline__ void proj_tile(
    const float* __restrict__ X, const float* __restrict__ W,
    const float* __restrict__ bias, float* __restrict__ Out,
    int m0, int n0, int t, ProjSmem& S)
{
    const int N = DD, K = DD;
    const int wid  = t >> 5;
    const int lane = t & 31;
    const int wm   = wid & 1;
    const int wn   = wid >> 1;
    const int grp  = lane >> 2;
    const int tig  = lane & 3;

    float acc[2][4][4];
    #pragma unroll
    for (int i = 0; i < 2; i++)
        #pragma unroll
        for (int j = 0; j < 4; j++)
            #pragma unroll
            for (int r = 0; r < 4; r++) acc[i][j][r] = 0.f;

    const int ar = t >> 2, ac = (t & 3) * 8;
    const int br = t >> 3, bc = (t & 7) * 16;

    const float* Xp = X + (size_t)(m0 + ar) * K + ac;
    const float* Wp = W + (size_t)br * N + n0 + bc;

    float4 pa0 = *(const float4*)(Xp);
    float4 pa1 = *(const float4*)(Xp + 4);
    float4 pb[4];
    #pragma unroll
    for (int u = 0; u < 4; u++) pb[u] = *(const float4*)(Wp + u*4);

    int buf = 0;
    for (int k0 = 0; k0 < K; k0 += 32) {
        {
            uint4 ua0 = { f2tf32(pa0.x), f2tf32(pa0.y), f2tf32(pa0.z), f2tf32(pa0.w) };
            uint4 ua1 = { f2tf32(pa1.x), f2tf32(pa1.y), f2tf32(pa1.z), f2tf32(pa1.w) };
            *(uint4*)&S.As[buf][ar][ac]     = ua0;
            *(uint4*)&S.As[buf][ar][ac + 4] = ua1;
            #pragma unroll
            for (int u = 0; u < 4; u++) {
                uint4 ub = { f2tf32(pb[u].x), f2tf32(pb[u].y), f2tf32(pb[u].z), f2tf32(pb[u].w) };
                *(uint4*)&S.Bsm[buf][br][bc + u*4] = ub;
            }
        }
        __syncthreads();

        if (k0 + 32 < K) {
            pa0 = *(const float4*)(Xp + k0 + 32);
            pa1 = *(const float4*)(Xp + k0 + 36);
            const float* wpn = Wp + (size_t)(k0 + 32) * N;
            #pragma unroll
            for (int u = 0; u < 4; u++) pb[u] = *(const float4*)(wpn + u*4);
        }

        #pragma unroll
        for (int ks = 0; ks < 4; ks++) {
            const int kb = ks * 8;
            uint32_t a[2][4];
            #pragma unroll
            for (int mi = 0; mi < 2; mi++) {
                const int mb = wm*32 + mi*16;
                a[mi][0] = S.As[buf][mb + grp    ][kb + tig];
                a[mi][1] = S.As[buf][mb + grp + 8][kb + tig];
                a[mi][2] = S.As[buf][mb + grp    ][kb + tig + 4];
                a[mi][3] = S.As[buf][mb + grp + 8][kb + tig + 4];
            }
            uint32_t b[4][2];
            #pragma unroll
            for (int ni = 0; ni < 4; ni++) {
                const int nb = wn*32 + ni*8;
                b[ni][0] = S.Bsm[buf][kb + tig    ][nb + grp];
                b[ni][1] = S.Bsm[buf][kb + tig + 4][nb + grp];
            }
            #pragma unroll
            for (int mi = 0; mi < 2; mi++)
                #pragma unroll
                for (int ni = 0; ni < 4; ni++)
                    mma_tf32(acc[mi][ni][0], acc[mi][ni][1], acc[mi][ni][2], acc[mi][ni][3],
                             a[mi][0], a[mi][1], a[mi][2], a[mi][3],
                             b[ni][0], b[ni][1]);
        }
        __syncthreads();
        buf ^= 1;
    }

    #pragma unroll
    for (int mi = 0; mi < 2; mi++) {
        #pragma unroll
        for (int ni = 0; ni < 4; ni++) {
            const int col = n0 + wn*32 + ni*8 + 2*tig;
            const float b0 = bias[col], b1 = bias[col+1];
            const int r0 = m0 + wm*32 + mi*16 + grp;
            const int r1 = r0 + 8;
            float2 lo = { acc[mi][ni][0] + b0, acc[mi][ni][1] + b1 };
            float2 hi = { acc[mi][ni][2] + b0, acc[mi][ni][3] + b1 };
            *(float2*)&Out[(size_t)r0 * N + col] = lo;
            *(float2*)&Out[(size_t)r1 * N + col] = hi;
        }
    }
}

// ---------------------------------------------------------------------------
// One 32q x 32k score tile: s = sum_d Ws[d]*tanh(q_d + k_d) + bs. MUFU-bound.
// 256 thr, 2x2 micro, D chunked by 64 through smem.
// ---------------------------------------------------------------------------
__device__ __forceinline__ void score_tile(
    const float* __restrict__ Ws, float bsv,
    int bz, int q0, int k0, int t, ScoreSmem& S)
{
    const int tx = t & 15, ty = t >> 4;

    float acc00 = 0.f, acc01 = 0.f, acc10 = 0.f, acc11 = 0.f;

    const float* qb = g_q + ((size_t)bz*LQ + q0) * DD;
    const float* kb = g_k + ((size_t)bz*LK + k0) * DD;

    const int lrow = t >> 3;
    const int lcol = (t & 7) * 8;

    for (int d0 = 0; d0 < DD; d0 += 64) {
        float4 x0 = *(const float4*)&qb[(size_t)lrow*DD + d0 + lcol];
        float4 x1 = *(const float4*)&qb[(size_t)lrow*DD + d0 + lcol + 4];
        S.Qs[lrow][lcol+0] = x0.x; S.Qs[lrow][lcol+1] = x0.y;
        S.Qs[lrow][lcol+2] = x0.z; S.Qs[lrow][lcol+3] = x0.w;
        S.Qs[lrow][lcol+4] = x1.x; S.Qs[lrow][lcol+5] = x1.y;
        S.Qs[lrow][lcol+6] = x1.z; S.Qs[lrow][lcol+7] = x1.w;
        float4 y0 = *(const float4*)&kb[(size_t)lrow*DD + d0 + lcol];
        float4 y1 = *(const float4*)&kb[(size_t)lrow*DD + d0 + lcol + 4];
        S.Ks[lrow][lcol+0] = y0.x; S.Ks[lrow][lcol+1] = y0.y;
        S.Ks[lrow][lcol+2] = y0.z; S.Ks[lrow][lcol+3] = y0.w;
        S.Ks[lrow][lcol+4] = y1.x; S.Ks[lrow][lcol+5] = y1.y;
        S.Ks[lrow][lcol+6] = y1.z; S.Ks[lrow][lcol+7] = y1.w;
        if (t < 16) *(float4*)&S.Wss[t*4] = *(const float4*)&Ws[d0 + t*4];
        __syncthreads();

        #pragma unroll 16
        for (int d = 0; d < 64; d++) {
            const float w  = S.Wss[d];
            const float qa = S.Qs[ty*2+0][d];
            const float qc = S.Qs[ty*2+1][d];
            const float ka = S.Ks[tx*2+0][d];
            const float kc = S.Ks[tx*2+1][d];
            acc00 = fmaf(w, tanh_fast(qa + ka), acc00);
            acc01 = fmaf(w, tanh_fast(qa + kc), acc01);
            acc10 = fmaf(w, tanh_fast(qc + ka), acc10);
            acc11 = fmaf(w, tanh_fast(qc + kc), acc11);
        }
        __syncthreads();
    }

    float* sp = g_scores + ((size_t)bz*LQ + q0) * LK + k0;
    sp[(ty*2+0)*LK + tx*2+0] = acc00 + bsv;
    sp[(ty*2+0)*LK + tx*2+1] = acc01 + bsv;
    sp[(ty*2+1)*LK + tx*2+0] = acc10 + bsv;
    sp[(ty*2+1)*LK + tx*2+1] = acc11 + bsv;
}

// ---------------------------------------------------------------------------
// proj for q,k (z selects). Grid (6, 16, 2).
// ---------------------------------------------------------------------------
__global__ __launch_bounds__(256) void proj_qk_kernel(
    const float* __restrict__ xq, const float* __restrict__ xk,
    const float* __restrict__ Wq, const float* __restrict__ bq,
    const float* __restrict__ Wk, const float* __restrict__ bk)
{
    __shared__ ProjSmem S;
    const float *X, *W, *bias;
    float* Out;
    if (blockIdx.z == 0) { X = xq; W = Wq; bias = bq; Out = g_q; }
    else                 { X = xk; W = Wk; bias = bk; Out = g_k; }
    proj_tile(X, W, bias, Out, blockIdx.y * 64, blockIdx.x * 128, threadIdx.x, S);
}

// ---------------------------------------------------------------------------
// Fused: blocks [0,256) = score tiles (MUFU pipe), blocks [256,352) = v
// projection tiles (tensor pipe). Independent work, overlapped on the chip.
// ---------------------------------------------------------------------------
__global__ __launch_bounds__(256) void fused_score_projv_kernel(
    const float* __restrict__ xv, const float* __restrict__ Wv, const float* __restrict__ bv,
    const float* __restrict__ Ws, const float* __restrict__ bsp)
{
    __shared__ union { ProjSmem pv; ScoreSmem sc; } S;
    const int bid = blockIdx.x;
    const int t   = threadIdx.x;

    if (bid < 256) {
        // score tile: bz (4) x q0 (8) x k0 (8)
        const int bz  = bid >> 6;
        const int rem = bid & 63;
        const int q0  = (rem >> 3) * 32;
        const int k0  = (rem & 7) * 32;
        score_tile(Ws, *bsp, bz, q0, k0, t, S.sc);
    } else {
        // v-projection tile: 96 = 6 n x 16 m
        const int p  = bid - 256;
        const int n0 = (p % 6) * 128;
        const int m0 = (p / 6) * 64;
        proj_tile(xv, Wv, bv, g_v, m0, n0, t, S.pv);
    }
}

// ---------------------------------------------------------------------------
// Row softmax over LK=256. One block (256 threads) per (b,q) row.
// ---------------------------------------------------------------------------
__global__ __launch_bounds__(256) void softmax_kernel(float* __restrict__ wout)
{
    const int row = blockIdx.x;
    const int t   = threadIdx.x;
    __shared__ float red[8];

    const float v = g_scores[(size_t)row*LK + t];

    float m = v;
    #pragma unroll
    for (int o = 16; o > 0; o >>= 1) m = fmaxf(m, __shfl_xor_sync(0xffffffffu, m, o));
    if ((t & 31) == 0) red[t >> 5] = m;
    __syncthreads();
    float mx = red[0];
    #pragma unroll
    for (int i = 1; i < 8; i++) mx = fmaxf(mx, red[i]);
    __syncthreads();

    const float e = __expf(v - mx);
    float s = e;
    #pragma unroll
    for (int o = 16; o > 0; o >>= 1) s += __shfl_xor_sync(0xffffffffu, s, o);
    if ((t & 31) == 0) red[t >> 5] = s;
    __syncthreads();
    float sum = 0.f;
    #pragma unroll
    for (int i = 0; i < 8; i++) sum += red[i];

    wout[(size_t)row*LK + t] = e * (1.0f / sum);
}

// ---------------------------------------------------------------------------
// attended = weights @ v via tf32 mma. Tile 32(q) x 128(d), 256 thr
// (8 warps: 1M x 8N, warp tile 32x16), BK=32 double-buffered. Grid (6,8,4).
// ---------------------------------------------------------------------------
__global__ __launch_bounds__(256) void av_kernel(const float* __restrict__ wts,
                                                 float* __restrict__ out)
{
    const int b  = blockIdx.z;
    const int q0 = blockIdx.y * 32;
    const int d0 = blockIdx.x * 128;

    __shared__ uint32_t As[2][32][36];
    __shared__ uint32_t Bsm[2][32][136];

    const int t    = threadIdx.x;
    const int wid  = t >> 5;
    const int lane = t & 31;
    const int grp  = lane >> 2;
    const int tig  = lane & 3;

    float acc[2][2][4];
    #pragma unroll
    for (int i = 0; i < 2; i++)
        #pragma unroll
        for (int j = 0; j < 2; j++)
            #pragma unroll
            for (int r = 0; r < 4; r++) acc[i][j][r] = 0.f;

    const int ar = t >> 3, ac = (t & 7) * 4;
    const int br = t >> 3, bc = (t & 7) * 16;

    const float* Ap = wts + ((size_t)b*LQ + q0 + ar) * LK + ac;
    const float* Bp = g_v + ((size_t)b*LK + br) * DD + d0 + bc;

    float4 pa = *(const float4*)(Ap);
    float4 pb[4];
    #pragma unroll
    for (int u = 0; u < 4; u++) pb[u] = *(const float4*)(Bp + u*4);

    int buf = 0;
    for (int j0 = 0; j0 < LK; j0 += 32) {
        {
            uint4 ua = { f2tf32(pa.x), f2tf32(pa.y), f2tf32(pa.z), f2tf32(pa.w) };
            *(uint4*)&As[buf][ar][ac] = ua;
            #pragma unroll
            for (int u = 0; u < 4; u++) {
                uint4 ub = { f2tf32(pb[u].x), f2tf32(pb[u].y), f2tf32(pb[u].z), f2tf32(pb[u].w) };
                *(uint4*)&Bsm[buf][br][bc + u*4] = ub;
            }
        }
        __syncthreads();

        if (j0 + 32 < LK) {
            pa = *(const float4*)(Ap + j0 + 32);
            const float* bpn = Bp + (size_t)(j0 + 32) * DD;
            #pragma unroll
            for (int u = 0; u < 4; u++) pb[u] = *(const float4*)(bpn + u*4);
        }

        #pragma unroll
        for (int ks = 0; ks < 4; ks++) {
            const int kb = ks * 8;
            uint32_t a[2][4];
            #pragma unroll
            for (int mi = 0; mi < 2; mi++) {
                const int mb = mi*16;
                a[mi][0] = As[buf][mb + grp    ][kb + tig];
                a[mi][1] = As[buf][mb + grp + 8][kb + tig];
                a[mi][2] = As[buf][mb + grp    ][kb + tig + 4];
                a[mi][3] = As[buf][mb + grp + 8][kb + tig + 4];
            }
            uint32_t bfr[2][2];
            #pragma unroll
            for (int ni = 0; ni < 2; ni++) {
                const int nb = wid*16 + ni*8;
                bfr[ni][0] = Bsm[buf][kb + tig    ][nb + grp];
                bfr[ni][1] = Bsm[buf][kb + tig + 4][nb + grp];
            }
            #pragma unroll
            for (int mi = 0; mi < 2; mi++)
                #pragma unroll
                for (int ni = 0; ni < 2; ni++)
                    mma_tf32(acc[mi][ni][0], acc[mi][ni][1], acc[mi][ni][2], acc[mi][ni][3],
                             a[mi][0], a[mi][1], a[mi][2], a[mi][3],
                             bfr[ni][0], bfr[ni][1]);
        }
        __syncthreads();
        buf ^= 1;
    }

    #pragma unroll
    for (int mi = 0; mi < 2; mi++) {
        #pragma unroll
        for (int ni = 0; ni < 2; ni++) {
            const int col = d0 + wid*16 + ni*8 + 2*tig;
            const int r0  = q0 + mi*16 + grp;
            const int r1  = r0 + 8;
            float2 lo = { acc[mi][ni][0], acc[mi][ni][1] };
            float2 hi = { acc[mi][ni][2], acc[mi][ni][3] };
            *(float2*)&out[((size_t)b*LQ + r0) * DD + col] = lo;
            *(float2*)&out[((size_t)b*LQ + r1) * DD + col] = hi;
        }
    }
}

// ---------------------------------------------------------------------------
extern "C" void kernel_launch(void* const* d_in, const int* in_sizes, int n_in,
                              void* d_out, int out_size)
{
    const float* query = (const float*)d_in[0];
    const float* key   = (const float*)d_in[1];
    const float* value = (const float*)d_in[2];
    const float* Wq    = (const float*)d_in[3];
    const float* bq    = (const float*)d_in[4];
    const float* Wk    = (const float*)d_in[5];
    const float* bk    = (const float*)d_in[6];
    const float* Wv    = (const float*)d_in[7];
    const float* bv    = (const float*)d_in[8];
    const float* Ws    = (const float*)d_in[9];
    const float* bs    = (const float*)d_in[10];

    float* att = (float*)d_out;                  // [B,LQ,D]
    float* wts = att + (size_t)BB * LQ * DD;     // [B,LQ,LK]

    // 1) q,k projections only (v deferred into the fused kernel)
    proj_qk_kernel<<<dim3(DD/128, (BB*LQ)/64, 2), 256>>>(query, key, Wq, bq, Wk, bk);

    // 2) score (MUFU) overlapped with v-projection (tensor)
    fused_score_projv_kernel<<<256 + 96, 256>>>(value, Wv, bv, Ws, bs);

    // 3) softmax -> attention_weights into d_out
    softmax_kernel<<<BB*LQ, 256>>>(wts);

    // 4) attended = weights @ v
    av_kernel<<<dim3(DD/128, LQ/32, BB), 256>>>(wts, att);
}

// round 9
// speedup vs baseline: 1.0160x; 1.0160x over previous
#include <cuda_runtime.h>
#include <cstdint>

#define BB 4
#define LQ 256
#define LK 256
#define DD 768

// Scratch (no cudaMalloc allowed)
__device__ float g_q[BB*LQ*DD];
__device__ float g_k[BB*LK*DD];
__device__ float g_v[BB*LK*DD];
__device__ float g_scores[BB*LQ*LK];

__device__ __forceinline__ float tanh_fast(float x) {
    float y;
    asm("tanh.approx.f32 %0, %1;" : "=f"(y) : "f"(x));
    return y;
}

// ---- tf32 helpers ----
__device__ __forceinline__ uint32_t f2tf32(float x) {
    uint32_t u;
    asm("cvt.rna.tf32.f32 %0, %1;" : "=r"(u) : "f"(x));
    return u;
}
__device__ __forceinline__ void mma_tf32(float& d0, float& d1, float& d2, float& d3,
                                         uint32_t a0, uint32_t a1, uint32_t a2, uint32_t a3,
                                         uint32_t b0, uint32_t b1) {
    asm("mma.sync.aligned.m16n8k8.row.col.f32.tf32.tf32.f32 "
        "{%0,%1,%2,%3}, {%4,%5,%6,%7}, {%8,%9}, {%0,%1,%2,%3};"
        : "+f"(d0), "+f"(d1), "+f"(d2), "+f"(d3)
        : "r"(a0), "r"(a1), "r"(a2), "r"(a3), "r"(b0), "r"(b1));
}

// ---------------------------------------------------------------------------
// Projection GEMM via tf32 mma (R6-proven). Out[M,N] = X[M,K]@W[K,N]+b.
// 64x128 tile, 256 thr (2Mx4N warps), BK=32 double-buffered. Grid (6,16,3).
// ---------------------------------------------------------------------------
__global__ __launch_bounds__(256) void proj_kernel(
    const float* __restrict__ xq, const float* __restrict__ xk, const float* __restrict__ xv,
    const float* __restrict__ Wq, const float* __restrict__ bq,
    const float* __restrict__ Wk, const float* __restrict__ bk,
    const float* __restrict__ Wv, const float* __restrict__ bv)
{
    const int N = DD, K = DD;
    const float *X, *W, *bias;
    float* Out;
    if (blockIdx.z == 0)      { X = xq; W = Wq; bias = bq; Out = g_q; }
    else if (blockIdx.z == 1) { X = xk; W = Wk; bias = bk; Out = g_k; }
    else                      { X = xv; W = Wv; bias = bv; Out = g_v; }

    __shared__ uint32_t As[2][64][36];
    __shared__ uint32_t Bsm[2][32][136];

    const int t    = threadIdx.x;
    const int wid  = t >> 5;
    const int lane = t & 31;
    const int wm   = wid & 1;
    const int wn   = wid >> 1;
    const int grp  = lane >> 2;
    const int tig  = lane & 3;

    const int m0 = blockIdx.y * 64;
    const int n0 = blockIdx.x * 128;

    float acc[2][4][4];
    #pragma unroll
    for (int i = 0; i < 2; i++)
        #pragma unroll
        for (int j = 0; j < 4; j++)
            #pragma unroll
            for (int r = 0; r < 4; r++) acc[i][j][r] = 0.f;

    const int ar = t >> 2, ac = (t & 3) * 8;
    const int br = t >> 3, bc = (t & 7) * 16;

    const float* Xp = X + (size_t)(m0 + ar) * K + ac;
    const float* Wp = W + (size_t)br * N + n0 + bc;

    float4 pa0 = *(const float4*)(Xp);
    float4 pa1 = *(const float4*)(Xp + 4);
    float4 pb[4];
    #pragma unroll
    for (int u = 0; u < 4; u++) pb[u] = *(const float4*)(Wp + u*4);

    int buf = 0;
    for (int k0 = 0; k0 < K; k0 += 32) {
        {
            uint4 ua0 = { f2tf32(pa0.x), f2tf32(pa0.y), f2tf32(pa0.z), f2tf32(pa0.w) };
            uint4 ua1 = { f2tf32(pa1.x), f2tf32(pa1.y), f2tf32(pa1.z), f2tf32(pa1.w) };
            *(uint4*)&As[buf][ar][ac]     = ua0;
            *(uint4*)&As[buf][ar][ac + 4] = ua1;
            #pragma unroll
            for (int u = 0; u < 4; u++) {
                uint4 ub = { f2tf32(pb[u].x), f2tf32(pb[u].y), f2tf32(pb[u].z), f2tf32(pb[u].w) };
                *(uint4*)&Bsm[buf][br][bc + u*4] = ub;
            }
        }
        __syncthreads();

        if (k0 + 32 < K) {
            pa0 = *(const float4*)(Xp + k0 + 32);
            pa1 = *(const float4*)(Xp + k0 + 36);
            const float* wpn = Wp + (size_t)(k0 + 32) * N;
            #pragma unroll
            for (int u = 0; u < 4; u++) pb[u] = *(const float4*)(wpn + u*4);
        }

        #pragma unroll
        for (int ks = 0; ks < 4; ks++) {
            const int kb = ks * 8;
            uint32_t a[2][4];
            #pragma unroll
            for (int mi = 0; mi < 2; mi++) {
                const int mb = wm*32 + mi*16;
                a[mi][0] = As[buf][mb + grp    ][kb + tig];
                a[mi][1] = As[buf][mb + grp + 8][kb + tig];
                a[mi][2] = As[buf][mb + grp    ][kb + tig + 4];
                a[mi][3] = As[buf][mb + grp + 8][kb + tig + 4];
            }
            uint32_t b[4][2];
            #pragma unroll
            for (int ni = 0; ni < 4; ni++) {
                const int nb = wn*32 + ni*8;
                b[ni][0] = Bsm[buf][kb + tig    ][nb + grp];
                b[ni][1] = Bsm[buf][kb + tig + 4][nb + grp];
            }
            #pragma unroll
            for (int mi = 0; mi < 2; mi++)
                #pragma unroll
                for (int ni = 0; ni < 4; ni++)
                    mma_tf32(acc[mi][ni][0], acc[mi][ni][1], acc[mi][ni][2], acc[mi][ni][3],
                             a[mi][0], a[mi][1], a[mi][2], a[mi][3],
                             b[ni][0], b[ni][1]);
        }
        __syncthreads();
        buf ^= 1;
    }

    #pragma unroll
    for (int mi = 0; mi < 2; mi++) {
        #pragma unroll
        for (int ni = 0; ni < 4; ni++) {
            const int col = n0 + wn*32 + ni*8 + 2*tig;
            const float b0 = bias[col], b1 = bias[col+1];
            const int r0 = m0 + wm*32 + mi*16 + grp;
            const int r1 = r0 + 8;
            float2 lo = { acc[mi][ni][0] + b0, acc[mi][ni][1] + b1 };
            float2 hi = { acc[mi][ni][2] + b0, acc[mi][ni][3] + b1 };
            *(float2*)&Out[(size_t)r0 * N + col] = lo;
            *(float2*)&Out[(size_t)r1 * N + col] = hi;
        }
    }
}

// ---------------------------------------------------------------------------
// Scores (static tiles, R6-proven): s = sum_d Ws[d]*tanh(q_d+k_d) + bs.
// 32x32 tile, 256 thr, 2x2 micro. Grid (8,8,4). MUFU-bound.
// ---------------------------------------------------------------------------
__global__ __launch_bounds__(256) void score_kernel(const float* __restrict__ Ws,
                                                    const float* __restrict__ bsp)
{
    const int bz = blockIdx.z;
    const int q0 = blockIdx.y * 32;
    const int k0 = blockIdx.x * 32;

    __shared__ float Qs[32][65];
    __shared__ float Ks[32][65];
    __shared__ float Wss[64];

    const int t  = threadIdx.x;
    const int tx = t & 15, ty = t >> 4;

    float acc00 = 0.f, acc01 = 0.f, acc10 = 0.f, acc11 = 0.f;

    const float* qb = g_q + ((size_t)bz*LQ + q0) * DD;
    const float* kb = g_k + ((size_t)bz*LK + k0) * DD;

    const int lrow = t >> 3;
    const int lcol = (t & 7) * 8;

    for (int d0 = 0; d0 < DD; d0 += 64) {
        float4 x0 = *(const float4*)&qb[(size_t)lrow*DD + d0 + lcol];
        float4 x1 = *(const float4*)&qb[(size_t)lrow*DD + d0 + lcol + 4];
        Qs[lrow][lcol+0] = x0.x; Qs[lrow][lcol+1] = x0.y;
        Qs[lrow][lcol+2] = x0.z; Qs[lrow][lcol+3] = x0.w;
        Qs[lrow][lcol+4] = x1.x; Qs[lrow][lcol+5] = x1.y;
        Qs[lrow][lcol+6] = x1.z; Qs[lrow][lcol+7] = x1.w;
        float4 y0 = *(const float4*)&kb[(size_t)lrow*DD + d0 + lcol];
        float4 y1 = *(const float4*)&kb[(size_t)lrow*DD + d0 + lcol + 4];
        Ks[lrow][lcol+0] = y0.x; Ks[lrow][lcol+1] = y0.y;
        Ks[lrow][lcol+2] = y0.z; Ks[lrow][lcol+3] = y0.w;
        Ks[lrow][lcol+4] = y1.x; Ks[lrow][lcol+5] = y1.y;
        Ks[lrow][lcol+6] = y1.z; Ks[lrow][lcol+7] = y1.w;
        if (t < 16) *(float4*)&Wss[t*4] = *(const float4*)&Ws[d0 + t*4];
        __syncthreads();

        #pragma unroll 16
        for (int d = 0; d < 64; d++) {
            const float w  = Wss[d];
            const float qa = Qs[ty*2+0][d];
            const float qc = Qs[ty*2+1][d];
            const float ka = Ks[tx*2+0][d];
            const float kc = Ks[tx*2+1][d];
            acc00 = fmaf(w, tanh_fast(qa + ka), acc00);
            acc01 = fmaf(w, tanh_fast(qa + kc), acc01);
            acc10 = fmaf(w, tanh_fast(qc + ka), acc10);
            acc11 = fmaf(w, tanh_fast(qc + kc), acc11);
        }
        __syncthreads();
    }

    const float bsv = *bsp;
    float* sp = g_scores + ((size_t)bz*LQ + q0) * LK + k0;
    sp[(ty*2+0)*LK + tx*2+0] = acc00 + bsv;
    sp[(ty*2+0)*LK + tx*2+1] = acc01 + bsv;
    sp[(ty*2+1)*LK + tx*2+0] = acc10 + bsv;
    sp[(ty*2+1)*LK + tx*2+1] = acc11 + bsv;
}

// ---------------------------------------------------------------------------
// Fused softmax + AV. Grid (6, 8, 4), 256 thr.
// Each block: softmax its 32 q-rows (from g_scores) in smem, write weights
// (blockIdx.x==0 only), convert in place to tf32, then 32q x 128d mma with
// A-frags straight from smem (no A staging) and V double-buffered.
// ---------------------------------------------------------------------------
__global__ __launch_bounds__(256) void avsm_kernel(float* __restrict__ wout,
                                                   float* __restrict__ out)
{
    const int b  = blockIdx.z;
    const int q0 = blockIdx.y * 32;
    const int d0 = blockIdx.x * 128;

    __shared__ float Sx[32][260];          // scores -> weights -> tf32 bits
    __shared__ uint32_t Bsm[2][32][136];   // V tiles (tf32)

    const int t    = threadIdx.x;
    const int wid  = t >> 5;               // warp 0..7 (= n-slot in mma)
    const int lane = t & 31;
    const int grp  = lane >> 2;
    const int tig  = lane & 3;

    // 1) load scores 32x256 (thread owns row srow, cols scol..scol+31)
    const int srow = t >> 3, scol = (t & 7) * 32;
    {
        const float* sp = g_scores + ((size_t)b*LQ + q0 + srow) * LK + scol;
        #pragma unroll
        for (int u = 0; u < 8; u++)
            *(float4*)&Sx[srow][scol + u*4] = *(const float4*)(sp + u*4);
    }
    __syncthreads();

    // 2) softmax: warp wid handles rows wid*4 .. wid*4+3
    #pragma unroll
    for (int r = 0; r < 4; r++) {
        const int row = wid*4 + r;
        float v[8];
        #pragma unroll
        for (int u = 0; u < 8; u++) v[u] = Sx[row][lane + u*32];
        float m = v[0];
        #pragma unroll
        for (int u = 1; u < 8; u++) m = fmaxf(m, v[u]);
        #pragma unroll
        for (int o = 16; o > 0; o >>= 1) m = fmaxf(m, __shfl_xor_sync(0xffffffffu, m, o));
        float s = 0.f;
        #pragma unroll
        for (int u = 0; u < 8; u++) { v[u] = __expf(v[u] - m); s += v[u]; }
        #pragma unroll
        for (int o = 16; o > 0; o >>= 1) s += __shfl_xor_sync(0xffffffffu, s, o);
        const float inv = 1.0f / s;
        #pragma unroll
        for (int u = 0; u < 8; u++) Sx[row][lane + u*32] = v[u] * inv;
    }
    __syncthreads();

    // 3) write weights output (only one d-block per q-range) — reads own cells
    if (blockIdx.x == 0) {
        float* wp = wout + ((size_t)b*LQ + q0 + srow) * LK + scol;
        #pragma unroll
        for (int u = 0; u < 8; u++)
            *(float4*)(wp + u*4) = *(const float4*)&Sx[srow][scol + u*4];
    }

    // 4) convert own cells to tf32 bits in place (same ownership as step 3)
    #pragma unroll 8
    for (int u = 0; u < 32; u++) {
        float* p = &Sx[srow][scol + u];
        *(uint32_t*)p = f2tf32(*p);
    }
    __syncthreads();

    // 5) mma: A from Sx (all K resident), B (V) double-buffered, BK=32
    float acc[2][2][4];
    #pragma unroll
    for (int i = 0; i < 2; i++)
        #pragma unroll
        for (int j = 0; j < 2; j++)
            #pragma unroll
            for (int r = 0; r < 4; r++) acc[i][j][r] = 0.f;

    const int br = t >> 3, bc = (t & 7) * 16;
    const float* Bp = g_v + ((size_t)b*LK + br) * DD + d0 + bc;

    float4 pb[4];
    #pragma unroll
    for (int u = 0; u < 4; u++) pb[u] = *(const float4*)(Bp + u*4);

    int buf = 0;
    for (int j0 = 0; j0 < LK; j0 += 32) {
        #pragma unroll
        for (int u = 0; u < 4; u++) {
            uint4 ub = { f2tf32(pb[u].x), f2tf32(pb[u].y), f2tf32(pb[u].z), f2tf32(pb[u].w) };
            *(uint4*)&Bsm[buf][br][bc + u*4] = ub;
        }
        __syncthreads();

        if (j0 + 32 < LK) {
            const float* bpn = Bp + (size_t)(j0 + 32) * DD;
            #pragma unroll
            for (int u = 0; u < 4; u++) pb[u] = *(const float4*)(bpn + u*4);
        }

        #pragma unroll
        for (int ks = 0; ks < 4; ks++) {
            const int kb = j0 + ks * 8;
            uint32_t a[2][4];
            #pragma unroll
            for (int mi = 0; mi < 2; mi++) {
                const int mb = mi*16;
                a[mi][0] = __float_as_uint(Sx[mb + grp    ][kb + tig]);
                a[mi][1] = __float_as_uint(Sx[mb + grp + 8][kb + tig]);
                a[mi][2] = __float_as_uint(Sx[mb + grp    ][kb + tig + 4]);
                a[mi][3] = __float_as_uint(Sx[mb + grp + 8][kb + tig + 4]);
            }
            uint32_t bfr[2][2];
            #pragma unroll
            for (int ni = 0; ni < 2; ni++) {
                const int nb = wid*16 + ni*8;
                bfr[ni][0] = Bsm[buf][ks*8 + tig    ][nb + grp];
                bfr[ni][1] = Bsm[buf][ks*8 + tig + 4][nb + grp];
            }
            #pragma unroll
            for (int mi = 0; mi < 2; mi++)
                #pragma unroll
                for (int ni = 0; ni < 2; ni++)
                    mma_tf32(acc[mi][ni][0], acc[mi][ni][1], acc[mi][ni][2], acc[mi][ni][3],
                             a[mi][0], a[mi][1], a[mi][2], a[mi][3],
                             bfr[ni][0], bfr[ni][1]);
        }
        __syncthreads();
        buf ^= 1;
    }

    #pragma unroll
    for (int mi = 0; mi < 2; mi++) {
        #pragma unroll
        for (int ni = 0; ni < 2; ni++) {
            const int col = d0 + wid*16 + ni*8 + 2*tig;
            const int r0  = q0 + mi*16 + grp;
            const int r1  = r0 + 8;
            float2 lo = { acc[mi][ni][0], acc[mi][ni][1] };
            float2 hi = { acc[mi][ni][2], acc[mi][ni][3] };
            *(float2*)&out[((size_t)b*LQ + r0) * DD + col] = lo;
            *(float2*)&out[((size_t)b*LQ + r1) * DD + col] = hi;
        }
    }
}

// ---------------------------------------------------------------------------
extern "C" void kernel_launch(void* const* d_in, const int* in_sizes, int n_in,
                              void* d_out, int out_size)
{
    const float* query = (const float*)d_in[0];
    const float* key   = (const float*)d_in[1];
    const float* value = (const float*)d_in[2];
    const float* Wq    = (const float*)d_in[3];
    const float* bq    = (const float*)d_in[4];
    const float* Wk    = (const float*)d_in[5];
    const float* bk    = (const float*)d_in[6];
    const float* Wv    = (const float*)d_in[7];
    const float* bv    = (const float*)d_in[8];
    const float* Ws    = (const float*)d_in[9];
    const float* bs    = (const float*)d_in[10];

    float* att = (float*)d_out;                  // [B,LQ,D]
    float* wts = att + (size_t)BB * LQ * DD;     // [B,LQ,LK]

    // 1) q,k,v projections (tf32 mma)
    proj_kernel<<<dim3(DD/128, (BB*LQ)/64, 3), 256>>>(
        query, key, value, Wq, bq, Wk, bk, Wv, bv);

    // 2) additive scores (MUFU floor)
    score_kernel<<<dim3(LK/32, LQ/32, BB), 256>>>(Ws, bs);

    // 3) fused softmax + attended (weights written by d-block 0)
    avsm_kernel<<<dim3(DD/128, LQ/32, BB), 256>>>(wts, att);
}

// round 11
// speedup vs baseline: 1.1989x; 1.1800x over previous
#include <cuda_runtime.h>
#include <cuda_pipeline.h>
#include <cstdint>

#define BB 4
#define LQ 256
#define LK 256
#define DD 768

// Scratch (no cudaMalloc allowed)
__device__ float g_q[BB*LQ*DD];
__device__ float g_k[BB*LK*DD];
__device__ float g_v[BB*LK*DD];
__device__ float g_scores[BB*LQ*LK];

__device__ __forceinline__ float tanh_fast(float x) {
    float y;
    asm("tanh.approx.f32 %0, %1;" : "=f"(y) : "f"(x));
    return y;
}

// ---- tf32 helpers ----
__device__ __forceinline__ uint32_t f2tf32(float x) {
    uint32_t u;
    asm("cvt.rna.tf32.f32 %0, %1;" : "=r"(u) : "f"(x));
    return u;
}
// round fp32 bits to nearest tf32 (mma keeps top 19 bits; +(1<<12) rounds
// half-up, mantissa carry correctly bumps the exponent)
__device__ __forceinline__ uint32_t rnd_tf32(uint32_t u) { return u + 0x1000u; }

__device__ __forceinline__ void mma_tf32(float& d0, float& d1, float& d2, float& d3,
                                         uint32_t a0, uint32_t a1, uint32_t a2, uint32_t a3,
                                         uint32_t b0, uint32_t b1) {
    asm("mma.sync.aligned.m16n8k8.row.col.f32.tf32.tf32.f32 "
        "{%0,%1,%2,%3}, {%4,%5,%6,%7}, {%8,%9}, {%0,%1,%2,%3};"
        : "+f"(d0), "+f"(d1), "+f"(d2), "+f"(d3)
        : "r"(a0), "r"(a1), "r"(a2), "r"(a3), "r"(b0), "r"(b1));
}
__device__ __forceinline__ void ldsm_x4(uint32_t& r0, uint32_t& r1, uint32_t& r2, uint32_t& r3,
                                        uint32_t addr) {
    asm volatile("ldmatrix.sync.aligned.m8n8.x4.shared.b16 {%0,%1,%2,%3}, [%4];"
                 : "=r"(r0), "=r"(r1), "=r"(r2), "=r"(r3) : "r"(addr));
}

// ---------------------------------------------------------------------------
// Projection GEMM: tf32 mma + cp.async staging + ldmatrix A-frags +
// register-side tf32 rounding. Out[M,N] = X[M,K]@W[K,N]+b.
// 64x128 tile, 256 thr (2Mx4N warps), BK=32 double-buffered. Grid (6,16,3).
// ---------------------------------------------------------------------------
__global__ __launch_bounds__(256, 3) void proj_kernel(
    const float* __restrict__ xq, const float* __restrict__ xk, const float* __restrict__ xv,
    const float* __restrict__ Wq, const float* __restrict__ bq,
    const float* __restrict__ Wk, const float* __restrict__ bk,
    const float* __restrict__ Wv, const float* __restrict__ bv)
{
    const int N = DD, K = DD;
    const float *X, *W, *bias;
    float* Out;
    if (blockIdx.z == 0)      { X = xq; W = Wq; bias = bq; Out = g_q; }
    else if (blockIdx.z == 1) { X = xk; W = Wk; bias = bk; Out = g_k; }
    else                      { X = xv; W = Wv; bias = bv; Out = g_v; }

    __shared__ uint32_t As[2][64][36];    // [m][k] raw fp32 bits
    __shared__ uint32_t Bsm[2][32][136];  // [k][n] raw fp32 bits

    const int t    = threadIdx.x;
    const int wid  = t >> 5;
    const int lane = t & 31;
    const int wm   = wid & 1;
    const int wn   = wid >> 1;
    const int grp  = lane >> 2;
    const int tig  = lane & 3;

    const int m0 = blockIdx.y * 64;
    const int n0 = blockIdx.x * 128;

    float acc[2][4][4];
    #pragma unroll
    for (int i = 0; i < 2; i++)
        #pragma unroll
        for (int j = 0; j < 4; j++)
            #pragma unroll
            for (int r = 0; r < 4; r++) acc[i][j][r] = 0.f;

    const int ar = t >> 2, ac = (t & 3) * 8;
    const int br = t >> 3, bc = (t & 7) * 16;

    const float* Xp = X + (size_t)(m0 + ar) * K + ac;
    const float* Wp = W + (size_t)br * N + n0 + bc;

    const int lrow = (lane & 7) + (lane & 8);   // 0..15
    const int lcol = (lane >> 4) * 4;           // 0 or 4
    const uint32_t a_addr0 =
        (uint32_t)__cvta_generic_to_shared(&As[0][wm*32 + lrow][lcol]);

    // prologue: stage tile 0
    __pipeline_memcpy_async(&As[0][ar][ac],     Xp,     16);
    __pipeline_memcpy_async(&As[0][ar][ac + 4], Xp + 4, 16);
    #pragma unroll
    for (int u = 0; u < 4; u++)
        __pipeline_memcpy_async(&Bsm[0][br][bc + u*4], Wp + u*4, 16);
    __pipeline_commit();

    for (int k0 = 0; k0 < K; k0 += 32) {
        const int buf = (k0 >> 5) & 1;
        if (k0 + 32 < K) {
            const int nb = buf ^ 1;
            __pipeline_memcpy_async(&As[nb][ar][ac],     Xp + k0 + 32, 16);
            __pipeline_memcpy_async(&As[nb][ar][ac + 4], Xp + k0 + 36, 16);
            const float* wpn = Wp + (size_t)(k0 + 32) * N;
            #pragma unroll
            for (int u = 0; u < 4; u++)
                __pipeline_memcpy_async(&Bsm[nb][br][bc + u*4], wpn + u*4, 16);
            __pipeline_commit();
            __pipeline_wait_prior(1);
        } else {
            __pipeline_wait_prior(0);
        }
        __syncthreads();

        #pragma unroll
        for (int ks = 0; ks < 4; ks++) {
            const int kb = ks * 8;
            uint32_t a[2][4];
            #pragma unroll
            for (int mi = 0; mi < 2; mi++) {
                const uint32_t ad = a_addr0 + (uint32_t)((buf*64*36 + mi*16*36 + kb) * 4);
                ldsm_x4(a[mi][0], a[mi][1], a[mi][2], a[mi][3], ad);
                #pragma unroll
                for (int r = 0; r < 4; r++) a[mi][r] = rnd_tf32(a[mi][r]);
            }
            uint32_t b[4][2];
            #pragma unroll
            for (int ni = 0; ni < 4; ni++) {
                const int nb2 = wn*32 + ni*8;
                b[ni][0] = rnd_tf32(Bsm[buf][kb + tig    ][nb2 + grp]);
                b[ni][1] = rnd_tf32(Bsm[buf][kb + tig + 4][nb2 + grp]);
            }
            #pragma unroll
            for (int mi = 0; mi < 2; mi++)
                #pragma unroll
                for (int ni = 0; ni < 4; ni++)
                    mma_tf32(acc[mi][ni][0], acc[mi][ni][1], acc[mi][ni][2], acc[mi][ni][3],
                             a[mi][0], a[mi][1], a[mi][2], a[mi][3],
                             b[ni][0], b[ni][1]);
        }
        __syncthreads();
    }

    #pragma unroll
    for (int mi = 0; mi < 2; mi++) {
        #pragma unroll
        for (int ni = 0; ni < 4; ni++) {
            const int col = n0 + wn*32 + ni*8 + 2*tig;
            const float b0 = bias[col], b1 = bias[col+1];
            const int r0 = m0 + wm*32 + mi*16 + grp;
            const int r1 = r0 + 8;
            float2 lo = { acc[mi][ni][0] + b0, acc[mi][ni][1] + b1 };
            float2 hi = { acc[mi][ni][2] + b0, acc[mi][ni][3] + b1 };
            *(float2*)&Out[(size_t)r0 * N + col] = lo;
            *(float2*)&Out[(size_t)r1 * N + col] = hi;
        }
    }
}

// ---------------------------------------------------------------------------
// Scores (MUFU floor): s = sum_d Ws[d]*tanh(q_d+k_d) + bs.
// 32x32 tile, 256 thr, 2x2 micro. Grid (8,8,4).
// ---------------------------------------------------------------------------
__global__ __launch_bounds__(256) void score_kernel(const float* __restrict__ Ws,
                                                    const float* __restrict__ bsp)
{
    const int bz = blockIdx.z;
    const int q0 = blockIdx.y * 32;
    const int k0 = blockIdx.x * 32;

    __shared__ float Qs[32][65];
    __shared__ float Ks[32][65];
    __shared__ float Wss[64];

    const int t  = threadIdx.x;
    const int tx = t & 15, ty = t >> 4;

    float acc00 = 0.f, acc01 = 0.f, acc10 = 0.f, acc11 = 0.f;

    const float* qb = g_q + ((size_t)bz*LQ + q0) * DD;
    const float* kb = g_k + ((size_t)bz*LK + k0) * DD;

    const int lrow = t >> 3;
    const int lcol = (t & 7) * 8;

    for (int d0 = 0; d0 < DD; d0 += 64) {
        float4 x0 = *(const float4*)&qb[(size_t)lrow*DD + d0 + lcol];
        float4 x1 = *(const float4*)&qb[(size_t)lrow*DD + d0 + lcol + 4];
        Qs[lrow][lcol+0] = x0.x; Qs[lrow][lcol+1] = x0.y;
        Qs[lrow][lcol+2] = x0.z; Qs[lrow][lcol+3] = x0.w;
        Qs[lrow][lcol+4] = x1.x; Qs[lrow][lcol+5] = x1.y;
        Qs[lrow][lcol+6] = x1.z; Qs[lrow][lcol+7] = x1.w;
        float4 y0 = *(const float4*)&kb[(size_t)lrow*DD + d0 + lcol];
        float4 y1 = *(const float4*)&kb[(size_t)lrow*DD + d0 + lcol + 4];
        Ks[lrow][lcol+0] = y0.x; Ks[lrow][lcol+1] = y0.y;
        Ks[lrow][lcol+2] = y0.z; Ks[lrow][lcol+3] = y0.w;
        Ks[lrow][lcol+4] = y1.x; Ks[lrow][lcol+5] = y1.y;
        Ks[lrow][lcol+6] = y1.z; Ks[lrow][lcol+7] = y1.w;
        if (t < 16) *(float4*)&Wss[t*4] = *(const float4*)&Ws[d0 + t*4];
        __syncthreads();

        #pragma unroll 16
        for (int d = 0; d < 64; d++) {
            const float w  = Wss[d];
            const float qa = Qs[ty*2+0][d];
            const float qc = Qs[ty*2+1][d];
            const float ka = Ks[tx*2+0][d];
            const float kc = Ks[tx*2+1][d];
            acc00 = fmaf(w, tanh_fast(qa + ka), acc00);
            acc01 = fmaf(w, tanh_fast(qa + kc), acc01);
            acc10 = fmaf(w, tanh_fast(qc + ka), acc10);
            acc11 = fmaf(w, tanh_fast(qc + kc), acc11);
        }
        __syncthreads();
    }

    const float bsv = *bsp;
    float* sp = g_scores + ((size_t)bz*LQ + q0) * LK + k0;
    sp[(ty*2+0)*LK + tx*2+0] = acc00 + bsv;
    sp[(ty*2+0)*LK + tx*2+1] = acc01 + bsv;
    sp[(ty*2+1)*LK + tx*2+0] = acc10 + bsv;
    sp[(ty*2+1)*LK + tx*2+1] = acc11 + bsv;
}

// ---------------------------------------------------------------------------
// Row softmax over LK=256. One block (256 threads) per (b,q) row.
// ---------------------------------------------------------------------------
__global__ __launch_bounds__(256) void softmax_kernel(float* __restrict__ wout)
{
    const int row = blockIdx.x;
    const int t   = threadIdx.x;
    __shared__ float red[8];

    const float v = g_scores[(size_t)row*LK + t];

    float m = v;
    #pragma unroll
    for (int o = 16; o > 0; o >>= 1) m = fmaxf(m, __shfl_xor_sync(0xffffffffu, m, o));
    if ((t & 31) == 0) red[t >> 5] = m;
    __syncthreads();
    float mx = red[0];
    #pragma unroll
    for (int i = 1; i < 8; i++) mx = fmaxf(mx, red[i]);
    __syncthreads();

    const float e = __expf(v - mx);
    float s = e;
    #pragma unroll
    for (int o = 16; o > 0; o >>= 1) s += __shfl_xor_sync(0xffffffffu, s, o);
    if ((t & 31) == 0) red[t >> 5] = s;
    __syncthreads();
    float sum = 0.f;
    #pragma unroll
    for (int i = 0; i < 8; i++) sum += red[i];

    wout[(size_t)row*LK + t] = e * (1.0f / sum);
}

// ---------------------------------------------------------------------------
// attended = weights @ v via tf32 mma (R7-proven, 18.5us). Tile 32q x 128d,
// 256 thr (8 warps: 1M x 8N, warp tile 32x16), BK=32 double-buffered,
// RNA cvt staging. Grid (6,8,4).
// ---------------------------------------------------------------------------
__global__ __launch_bounds__(256) void av_kernel(const float* __restrict__ wts,
                                                 float* __restrict__ out)
{
    const int b  = blockIdx.z;
    const int q0 = blockIdx.y * 32;
    const int d0 = blockIdx.x * 128;

    __shared__ uint32_t As[2][32][36];
    __shared__ uint32_t Bsm[2][32][136];

    const int t    = threadIdx.x;
    const int wid  = t >> 5;
    const int lane = t & 31;
    const int grp  = lane >> 2;
    const int tig  = lane & 3;

    float acc[2][2][4];
    #pragma unroll
    for (int i = 0; i < 2; i++)
        #pragma unroll
        for (int j = 0; j < 2; j++)
            #pragma unroll
            for (int r = 0; r < 4; r++) acc[i][j][r] = 0.f;

    const int ar = t >> 3, ac = (t & 7) * 4;
    const int br = t >> 3, bc = (t & 7) * 16;

    const float* Ap = wts + ((size_t)b*LQ + q0 + ar) * LK + ac;
    const float* Bp = g_v + ((size_t)b*LK + br) * DD + d0 + bc;

    float4 pa = *(const float4*)(Ap);
    float4 pb[4];
    #pragma unroll
    for (int u = 0; u < 4; u++) pb[u] = *(const float4*)(Bp + u*4);

    int buf = 0;
    for (int j0 = 0; j0 < LK; j0 += 32) {
        {
            uint4 ua = { f2tf32(pa.x), f2tf32(pa.y), f2tf32(pa.z), f2tf32(pa.w) };
            *(uint4*)&As[buf][ar][ac] = ua;
            #pragma unroll
            for (int u = 0; u < 4; u++) {
                uint4 ub = { f2tf32(pb[u].x), f2tf32(pb[u].y), f2tf32(pb[u].z), f2tf32(pb[u].w) };
                *(uint4*)&Bsm[buf][br][bc + u*4] = ub;
            }
        }
        __syncthreads();

        if (j0 + 32 < LK) {
            pa = *(const float4*)(Ap + j0 + 32);
            const float* bpn = Bp + (size_t)(j0 + 32) * DD;
            #pragma unroll
            for (int u = 0; u < 4; u++) pb[u] = *(const float4*)(bpn + u*4);
        }

        #pragma unroll
        for (int ks = 0; ks < 4; ks++) {
            const int kb = ks * 8;
            uint32_t a[2][4];
            #pragma unroll
            for (int mi = 0; mi < 2; mi++) {
                const int mb = mi*16;
                a[mi][0] = As[buf][mb + grp    ][kb + tig];
                a[mi][1] = As[buf][mb + grp + 8][kb + tig];
                a[mi][2] = As[buf][mb + grp    ][kb + tig + 4];
                a[mi][3] = As[buf][mb + grp + 8][kb + tig + 4];
            }
            uint32_t bfr[2][2];
            #pragma unroll
            for (int ni = 0; ni < 2; ni++) {
                const int nb = wid*16 + ni*8;
                bfr[ni][0] = Bsm[buf][kb + tig    ][nb + grp];
                bfr[ni][1] = Bsm[buf][kb + tig + 4][nb + grp];
            }
            #pragma unroll
            for (int mi = 0; mi < 2; mi++)
                #pragma unroll
                for (int ni = 0; ni < 2; ni++)
                    mma_tf32(acc[mi][ni][0], acc[mi][ni][1], acc[mi][ni][2], acc[mi][ni][3],
                             a[mi][0], a[mi][1], a[mi][2], a[mi][3],
                             bfr[ni][0], bfr[ni][1]);
        }
        __syncthreads();
        buf ^= 1;
    }

    #pragma unroll
    for (int mi = 0; mi < 2; mi++) {
        #pragma unroll
        for (int ni = 0; ni < 2; ni++) {
            const int col = d0 + wid*16 + ni*8 + 2*tig;
            const int r0  = q0 + mi*16 + grp;
            const int r1  = r0 + 8;
            float2 lo = { acc[mi][ni][0], acc[mi][ni][1] };
            float2 hi = { acc[mi][ni][2], acc[mi][ni][3] };
            *(float2*)&out[((size_t)b*LQ + r0) * DD + col] = lo;
            *(float2*)&out[((size_t)b*LQ + r1) * DD + col] = hi;
        }
    }
}

// ---------------------------------------------------------------------------
extern "C" void kernel_launch(void* const* d_in, const int* in_sizes, int n_in,
                              void* d_out, int out_size)
{
    const float* query = (const float*)d_in[0];
    const float* key   = (const float*)d_in[1];
    const float* value = (const float*)d_in[2];
    const float* Wq    = (const float*)d_in[3];
    const float* bq    = (const float*)d_in[4];
    const float* Wk    = (const float*)d_in[5];
    const float* bk    = (const float*)d_in[6];
    const float* Wv    = (const float*)d_in[7];
    const float* bv    = (const float*)d_in[8];
    const float* Ws    = (const float*)d_in[9];
    const float* bs    = (const float*)d_in[10];

    float* att = (float*)d_out;                  // [B,LQ,D]
    float* wts = att + (size_t)BB * LQ * DD;     // [B,LQ,LK]

    // 1) q,k,v projections (tf32 mma + cp.async + ldmatrix + reg-rounding)
    proj_kernel<<<dim3(DD/128, (BB*LQ)/64, 3), 256>>>(
        query, key, value, Wq, bq, Wk, bk, Wv, bv);

    // 2) additive scores (MUFU floor)
    score_kernel<<<dim3(LK/32, LQ/32, BB), 256>>>(Ws, bs);

    // 3) softmax -> attention_weights into d_out
    softmax_kernel<<<BB*LQ, 256>>>(wts);

    // 4) attended = weights @ v (tf32 mma)
    av_kernel<<<dim3(DD/128, LQ/32, BB), 256>>>(wts, att);
}

// round 12
// speedup vs baseline: 1.5751x; 1.3138x over previous
#include <cuda_runtime.h>
#include <cuda_fp16.h>
#include <cuda_pipeline.h>
#include <cstdint>

#define BB 4
#define LQ 256
#define LK 256
#define DD 768

// Scratch (no cudaMalloc allowed)
__device__ float  g_q[BB*LQ*DD];
__device__ float  g_k[BB*LK*DD];
__device__ __half g_vh[BB*LK*DD];        // v projection output (fp16, feeds av)
__device__ __half g_xh[3][BB*LQ*DD];     // fp16 copies of query,key,value inputs
__device__ __half g_wh[3][DD*DD];        // fp16 copies of Wq,Wk,Wv
__device__ float  g_scores[BB*LQ*LK];

__device__ __forceinline__ float tanh_fast(float x) {
    float y;
    asm("tanh.approx.f32 %0, %1;" : "=f"(y) : "f"(x));
    return y;
}

// ---- fp16 mma helpers ----
__device__ __forceinline__ void mma_f16(float& d0, float& d1, float& d2, float& d3,
                                        uint32_t a0, uint32_t a1, uint32_t a2, uint32_t a3,
                                        uint32_t b0, uint32_t b1) {
    asm("mma.sync.aligned.m16n8k16.row.col.f32.f16.f16.f32 "
        "{%0,%1,%2,%3}, {%4,%5,%6,%7}, {%8,%9}, {%0,%1,%2,%3};"
        : "+f"(d0), "+f"(d1), "+f"(d2), "+f"(d3)
        : "r"(a0), "r"(a1), "r"(a2), "r"(a3), "r"(b0), "r"(b1));
}
__device__ __forceinline__ void ldsm_x4(uint32_t& r0, uint32_t& r1, uint32_t& r2, uint32_t& r3,
                                        uint32_t addr) {
    asm volatile("ldmatrix.sync.aligned.m8n8.x4.shared.b16 {%0,%1,%2,%3}, [%4];"
                 : "=r"(r0), "=r"(r1), "=r"(r2), "=r"(r3) : "r"(addr));
}
__device__ __forceinline__ void ldsm_x4_t(uint32_t& r0, uint32_t& r1, uint32_t& r2, uint32_t& r3,
                                          uint32_t addr) {
    asm volatile("ldmatrix.sync.aligned.m8n8.x4.trans.shared.b16 {%0,%1,%2,%3}, [%4];"
                 : "=r"(r0), "=r"(r1), "=r"(r2), "=r"(r3) : "r"(addr));
}

// ---------------------------------------------------------------------------
// Convert the 6 fp32 operand arrays to fp16 once. Grid (384, 6), 256 thr.
// ---------------------------------------------------------------------------
__global__ __launch_bounds__(256) void cvt_kernel(
    const float* __restrict__ xq, const float* __restrict__ xk, const float* __restrict__ xv,
    const float* __restrict__ Wq, const float* __restrict__ Wk, const float* __restrict__ Wv)
{
    const int id = blockIdx.y;
    const float* src;
    __half* dst;
    int n;
    if (id < 3) {
        src = (id == 0) ? xq : (id == 1) ? xk : xv;
        dst = g_xh[id];
        n = BB * LQ * DD;
    } else {
        src = (id == 3) ? Wq : (id == 4) ? Wk : Wv;
        dst = g_wh[id - 3];
        n = DD * DD;
    }
    const int idx = (blockIdx.x * 256 + threadIdx.x) * 8;
    if (idx >= n) return;
    float4 a = *(const float4*)(src + idx);
    float4 b = *(const float4*)(src + idx + 4);
    __half2 h0 = __floats2half2_rn(a.x, a.y);
    __half2 h1 = __floats2half2_rn(a.z, a.w);
    __half2 h2 = __floats2half2_rn(b.x, b.y);
    __half2 h3 = __floats2half2_rn(b.z, b.w);
    uint4 o;
    o.x = *(const uint32_t*)&h0;
    o.y = *(const uint32_t*)&h1;
    o.z = *(const uint32_t*)&h2;
    o.w = *(const uint32_t*)&h3;
    *(uint4*)(dst + idx) = o;
}

// ---------------------------------------------------------------------------
// Projection GEMM via fp16 mma (m16n8k16) + cp.async of pre-converted fp16.
// Out[M,N] = X[M,K]@W[K,N]+b, M=1024, N=K=768. 64x128 tile, 256 thr
// (2Mx4N warps, warp tile 32x32), BK=32 double-buffered. Grid (6,16,3).
// z==2 (v) writes fp16 output (only feeds av).
// ---------------------------------------------------------------------------
__global__ __launch_bounds__(256) void proj_kernel(
    const float* __restrict__ bq, const float* __restrict__ bk, const float* __restrict__ bv)
{
    const int z = blockIdx.z;
    const __half* X = g_xh[z];
    const __half* W = g_wh[z];
    const float* bias = (z == 0) ? bq : (z == 1) ? bk : bv;

    __shared__ __half As[2][64][40];     // [m][k], row 80B (20 banks, conflict-free ldsm)
    __shared__ __half Bsm[2][32][136];   // [k][n], row 272B (4-bank stride, conflict-free)

    const int t    = threadIdx.x;
    const int wid  = t >> 5;
    const int lane = t & 31;
    const int wm   = wid & 1;
    const int wn   = wid >> 1;
    const int grp  = lane >> 2;
    const int tig  = lane & 3;

    const int m0 = blockIdx.y * 64;
    const int n0 = blockIdx.x * 128;

    float acc[2][4][4];
    #pragma unroll
    for (int i = 0; i < 2; i++)
        #pragma unroll
        for (int j = 0; j < 4; j++)
            #pragma unroll
            for (int r = 0; r < 4; r++) acc[i][j][r] = 0.f;

    // staging: A 64x32 halves (16B/thread), B 32x128 halves (2x16B/thread)
    const int ar = t >> 2, acs = (t & 3) * 8;
    const int br = t >> 3, bcs = (t & 7) * 16;

    const __half* Xp = X + (size_t)(m0 + ar) * DD + acs;
    const __half* Wp = W + (size_t)br * DD + n0 + bcs;

    // ldmatrix addresses
    const int lrow = lane & 15;          // A row within 16-block
    const int lca  = (lane >> 4) * 8;    // A col half-select
    const uint32_t a_addr0 =
        (uint32_t)__cvta_generic_to_shared(&As[0][wm*32 + lrow][lca]);
    const int brow = ((lane >> 3) & 1) * 8 + (lane & 7);   // (m&1)*8 + r
    const int bcol = (lane >> 4) * 8;                      // (m>>1)*8
    const uint32_t b_addr0 =
        (uint32_t)__cvta_generic_to_shared(&Bsm[0][brow][wn*32 + bcol]);

    // prologue: stage tile 0
    __pipeline_memcpy_async(&As[0][ar][acs], Xp, 16);
    __pipeline_memcpy_async(&Bsm[0][br][bcs],     Wp,     16);
    __pipeline_memcpy_async(&Bsm[0][br][bcs + 8], Wp + 8, 16);
    __pipeline_commit();

    for (int k0 = 0; k0 < DD; k0 += 32) {
        const int buf = (k0 >> 5) & 1;
        if (k0 + 32 < DD) {
            const int nb = buf ^ 1;
            __pipeline_memcpy_async(&As[nb][ar][acs], Xp + k0 + 32, 16);
            const __half* wpn = Wp + (size_t)(k0 + 32) * DD;
            __pipeline_memcpy_async(&Bsm[nb][br][bcs],     wpn,     16);
            __pipeline_memcpy_async(&Bsm[nb][br][bcs + 8], wpn + 8, 16);
            __pipeline_commit();
            __pipeline_wait_prior(1);
        } else {
            __pipeline_wait_prior(0);
        }
        __syncthreads();

        #pragma unroll
        for (int ks = 0; ks < 2; ks++) {
            uint32_t a[2][4];
            #pragma unroll
            for (int mi = 0; mi < 2; mi++) {
                const uint32_t ad = a_addr0 + (uint32_t)(buf*5120 + mi*1280 + ks*32);
                ldsm_x4(a[mi][0], a[mi][1], a[mi][2], a[mi][3], ad);
            }
            uint32_t b[4][2];
            #pragma unroll
            for (int p = 0; p < 2; p++) {
                const uint32_t bd = b_addr0 + (uint32_t)(buf*8704 + ks*4352 + p*32);
                ldsm_x4_t(b[p*2][0], b[p*2][1], b[p*2+1][0], b[p*2+1][1], bd);
            }
            #pragma unroll
            for (int mi = 0; mi < 2; mi++)
                #pragma unroll
                for (int ni = 0; ni < 4; ni++)
                    mma_f16(acc[mi][ni][0], acc[mi][ni][1], acc[mi][ni][2], acc[mi][ni][3],
                            a[mi][0], a[mi][1], a[mi][2], a[mi][3],
                            b[ni][0], b[ni][1]);
        }
        __syncthreads();
    }

    #pragma unroll
    for (int mi = 0; mi < 2; mi++) {
        #pragma unroll
        for (int ni = 0; ni < 4; ni++) {
            const int col = n0 + wn*32 + ni*8 + 2*tig;
            const float b0 = bias[col], b1 = bias[col+1];
            const int r0 = m0 + wm*32 + mi*16 + grp;
            const int r1 = r0 + 8;
            const float c00 = acc[mi][ni][0] + b0, c01 = acc[mi][ni][1] + b1;
            const float c10 = acc[mi][ni][2] + b0, c11 = acc[mi][ni][3] + b1;
            if (z < 2) {
                float* Out = (z == 0) ? g_q : g_k;
                float2 lo = { c00, c01 };
                float2 hi = { c10, c11 };
                *(float2*)&Out[(size_t)r0 * DD + col] = lo;
                *(float2*)&Out[(size_t)r1 * DD + col] = hi;
            } else {
                __half2 lo = __floats2half2_rn(c00, c01);
                __half2 hi = __floats2half2_rn(c10, c11);
                *(__half2*)&g_vh[(size_t)r0 * DD + col] = lo;
                *(__half2*)&g_vh[(size_t)r1 * DD + col] = hi;
            }
        }
    }
}

// ---------------------------------------------------------------------------
// Scores (MUFU floor): s = sum_d Ws[d]*tanh(q_d+k_d) + bs.
// 32x32 tile, 256 thr, 2x2 micro. Grid (8,8,4).
// ---------------------------------------------------------------------------
__global__ __launch_bounds__(256) void score_kernel(const float* __restrict__ Ws,
                                                    const float* __restrict__ bsp)
{
    const int bz = blockIdx.z;
    const int q0 = blockIdx.y * 32;
    const int k0 = blockIdx.x * 32;

    __shared__ float Qs[32][65];
    __shared__ float Ks[32][65];
    __shared__ float Wss[64];

    const int t  = threadIdx.x;
    const int tx = t & 15, ty = t >> 4;

    float acc00 = 0.f, acc01 = 0.f, acc10 = 0.f, acc11 = 0.f;

    const float* qb = g_q + ((size_t)bz*LQ + q0) * DD;
    const float* kb = g_k + ((size_t)bz*LK + k0) * DD;

    const int lrow = t >> 3;
    const int lcol = (t & 7) * 8;

    for (int d0 = 0; d0 < DD; d0 += 64) {
        float4 x0 = *(const float4*)&qb[(size_t)lrow*DD + d0 + lcol];
        float4 x1 = *(const float4*)&qb[(size_t)lrow*DD + d0 + lcol + 4];
        Qs[lrow][lcol+0] = x0.x; Qs[lrow][lcol+1] = x0.y;
        Qs[lrow][lcol+2] = x0.z; Qs[lrow][lcol+3] = x0.w;
        Qs[lrow][lcol+4] = x1.x; Qs[lrow][lcol+5] = x1.y;
        Qs[lrow][lcol+6] = x1.z; Qs[lrow][lcol+7] = x1.w;
        float4 y0 = *(const float4*)&kb[(size_t)lrow*DD + d0 + lcol];
        float4 y1 = *(const float4*)&kb[(size_t)lrow*DD + d0 + lcol + 4];
        Ks[lrow][lcol+0] = y0.x; Ks[lrow][lcol+1] = y0.y;
        Ks[lrow][lcol+2] = y0.z; Ks[lrow][lcol+3] = y0.w;
        Ks[lrow][lcol+4] = y1.x; Ks[lrow][lcol+5] = y1.y;
        Ks[lrow][lcol+6] = y1.z; Ks[lrow][lcol+7] = y1.w;
        if (t < 16) *(float4*)&Wss[t*4] = *(const float4*)&Ws[d0 + t*4];
        __syncthreads();

        #pragma unroll 16
        for (int d = 0; d < 64; d++) {
            const float w  = Wss[d];
            const float qa = Qs[ty*2+0][d];
            const float qc = Qs[ty*2+1][d];
            const float ka = Ks[tx*2+0][d];
            const float kc = Ks[tx*2+1][d];
            acc00 = fmaf(w, tanh_fast(qa + ka), acc00);
            acc01 = fmaf(w, tanh_fast(qa + kc), acc01);
            acc10 = fmaf(w, tanh_fast(qc + ka), acc10);
            acc11 = fmaf(w, tanh_fast(qc + kc), acc11);
        }
        __syncthreads();
    }

    const float bsv = *bsp;
    float* sp = g_scores + ((size_t)bz*LQ + q0) * LK + k0;
    sp[(ty*2+0)*LK + tx*2+0] = acc00 + bsv;
    sp[(ty*2+0)*LK + tx*2+1] = acc01 + bsv;
    sp[(ty*2+1)*LK + tx*2+0] = acc10 + bsv;
    sp[(ty*2+1)*LK + tx*2+1] = acc11 + bsv;
}

// ---------------------------------------------------------------------------
// Row softmax over LK=256. One block (256 threads) per (b,q) row.
// ---------------------------------------------------------------------------
__global__ __launch_bounds__(256) void softmax_kernel(float* __restrict__ wout)
{
    const int row = blockIdx.x;
    const int t   = threadIdx.x;
    __shared__ float red[8];

    const float v = g_scores[(size_t)row*LK + t];

    float m = v;
    #pragma unroll
    for (int o = 16; o > 0; o >>= 1) m = fmaxf(m, __shfl_xor_sync(0xffffffffu, m, o));
    if ((t & 31) == 0) red[t >> 5] = m;
    __syncthreads();
    float mx = red[0];
    #pragma unroll
    for (int i = 1; i < 8; i++) mx = fmaxf(mx, red[i]);
    __syncthreads();

    const float e = __expf(v - mx);
    float s = e;
    #pragma unroll
    for (int o = 16; o > 0; o >>= 1) s += __shfl_xor_sync(0xffffffffu, s, o);
    if ((t & 31) == 0) red[t >> 5] = s;
    __syncthreads();
    float sum = 0.f;
    #pragma unroll
    for (int i = 0; i < 8; i++) sum += red[i];

    wout[(size_t)row*LK + t] = e * (1.0f / sum);
}

// ---------------------------------------------------------------------------
// attended = weights @ v via fp16 mma. Tile 32q x 128d, 256 thr (8 warps:
// 1M x 8N, warp tile 32x16), BK=32 double-buffered. Weights cvt'd to fp16 in
// staging; V read as fp16 via cp.async. Grid (6,8,4).
// ---------------------------------------------------------------------------
__global__ __launch_bounds__(256) void av_kernel(const float* __restrict__ wts,
                                                 float* __restrict__ out)
{
    const int b  = blockIdx.z;
    const int q0 = blockIdx.y * 32;
    const int d0 = blockIdx.x * 128;

    __shared__ __half As[2][32][40];     // weights [q][j]
    __shared__ __half Bsm[2][32][136];   // V [j][d]

    const int t    = threadIdx.x;
    const int wid  = t >> 5;
    const int lane = t & 31;
    const int grp  = lane >> 2;
    const int tig  = lane & 3;

    float acc[2][2][4];
    #pragma unroll
    for (int i = 0; i < 2; i++)
        #pragma unroll
        for (int j = 0; j < 2; j++)
            #pragma unroll
            for (int r = 0; r < 4; r++) acc[i][j][r] = 0.f;

    // staging: A 32x32 fp32->fp16 (4 floats/thread), B 32x128 halves (2x16B/thread)
    const int ar = t >> 3, ac4 = (t & 7) * 4;
    const int br = t >> 3, bcs = (t & 7) * 16;

    const float*  Ap = wts + ((size_t)b*LQ + q0 + ar) * LK + ac4;
    const __half* Bp = g_vh + ((size_t)b*LK + br) * DD + d0 + bcs;

    // ldmatrix addresses
    const int lrow = lane & 15;
    const int lca  = (lane >> 4) * 8;
    const uint32_t a_addr0 = (uint32_t)__cvta_generic_to_shared(&As[0][lrow][lca]);
    const int brow = ((lane >> 3) & 1) * 8 + (lane & 7);
    const int bcol = (lane >> 4) * 8;
    const uint32_t b_addr0 =
        (uint32_t)__cvta_generic_to_shared(&Bsm[0][brow][wid*16 + bcol]);

    // prologue
    float4 pa = *(const float4*)(Ap);
    __pipeline_memcpy_async(&Bsm[0][br][bcs],     Bp,     16);
    __pipeline_memcpy_async(&Bsm[0][br][bcs + 8], Bp + 8, 16);
    __pipeline_commit();

    for (int j0 = 0; j0 < LK; j0 += 32) {
        const int buf = (j0 >> 5) & 1;
        // store A (cvt to fp16)
        {
            __half2 h0 = __floats2half2_rn(pa.x, pa.y);
            __half2 h1 = __floats2half2_rn(pa.z, pa.w);
            uint2 o = { *(const uint32_t*)&h0, *(const uint32_t*)&h1 };
            *(uint2*)&As[buf][ar][ac4] = o;
        }
        if (j0 + 32 < LK) {
            const int nb = buf ^ 1;
            pa = *(const float4*)(Ap + j0 + 32);
            const __half* bpn = Bp + (size_t)(j0 + 32) * DD;
            __pipeline_memcpy_async(&Bsm[nb][br][bcs],     bpn,     16);
            __pipeline_memcpy_async(&Bsm[nb][br][bcs + 8], bpn + 8, 16);
            __pipeline_commit();
            __pipeline_wait_prior(1);
        } else {
            __pipeline_wait_prior(0);
        }
        __syncthreads();

        #pragma unroll
        for (int ks = 0; ks < 2; ks++) {
            uint32_t a[2][4];
            #pragma unroll
            for (int mi = 0; mi < 2; mi++) {
                const uint32_t ad = a_addr0 + (uint32_t)(buf*2560 + mi*1280 + ks*32);
                ldsm_x4(a[mi][0], a[mi][1], a[mi][2], a[mi][3], ad);
            }
            uint32_t bf[2][2];
            {
                const uint32_t bd = b_addr0 + (uint32_t)(buf*8704 + ks*4352);
                ldsm_x4_t(bf[0][0], bf[0][1], bf[1][0], bf[1][1], bd);
            }
            #pragma unroll
            for (int mi = 0; mi < 2; mi++)
                #pragma unroll
                for (int ni = 0; ni < 2; ni++)
                    mma_f16(acc[mi][ni][0], acc[mi][ni][1], acc[mi][ni][2], acc[mi][ni][3],
                            a[mi][0], a[mi][1], a[mi][2], a[mi][3],
                            bf[ni][0], bf[ni][1]);
        }
        __syncthreads();
    }

    #pragma unroll
    for (int mi = 0; mi < 2; mi++) {
        #pragma unroll
        for (int ni = 0; ni < 2; ni++) {
            const int col = d0 + wid*16 + ni*8 + 2*tig;
            const int r0  = q0 + mi*16 + grp;
            const int r1  = r0 + 8;
            float2 lo = { acc[mi][ni][0], acc[mi][ni][1] };
            float2 hi = { acc[mi][ni][2], acc[mi][ni][3] };
            *(float2*)&out[((size_t)b*LQ + r0) * DD + col] = lo;
            *(float2*)&out[((size_t)b*LQ + r1) * DD + col] = hi;
        }
    }
}

// ---------------------------------------------------------------------------
extern "C" void kernel_launch(void* const* d_in, const int* in_sizes, int n_in,
                              void* d_out, int out_size)
{
    const float* query = (const float*)d_in[0];
    const float* key   = (const float*)d_in[1];
    const float* value = (const float*)d_in[2];
    const float* Wq    = (const float*)d_in[3];
    const float* bq    = (const float*)d_in[4];
    const float* Wk    = (const float*)d_in[5];
    const float* bk    = (const float*)d_in[6];
    const float* Wv    = (const float*)d_in[7];
    const float* bv    = (const float*)d_in[8];
    const float* Ws    = (const float*)d_in[9];
    const float* bs    = (const float*)d_in[10];

    float* att = (float*)d_out;                  // [B,LQ,D]
    float* wts = att + (size_t)BB * LQ * DD;     // [B,LQ,LK]

    // 0) fp32 -> fp16 operand conversion (once)
    cvt_kernel<<<dim3(384, 6), 256>>>(query, key, value, Wq, Wk, Wv);

    // 1) q,k,v projections (fp16 mma; v output in fp16)
    proj_kernel<<<dim3(DD/128, (BB*LQ)/64, 3), 256>>>(bq, bk, bv);

    // 2) additive scores (MUFU floor)
    score_kernel<<<dim3(LK/32, LQ/32, BB), 256>>>(Ws, bs);

    // 3) softmax -> attention_weights into d_out
    softmax_kernel<<<BB*LQ, 256>>>(wts);

    // 4) attended = weights @ v (fp16 mma)
    av_kernel<<<dim3(DD/128, LQ/32, BB), 256>>>(wts, att);
}

// round 13
// speedup vs baseline: 1.6690x; 1.0596x over previous
#include <cuda_runtime.h>
#include <cuda_fp16.h>
#include <cuda_pipeline.h>
#include <cstdint>

#define BB 4
#define LQ 256
#define LK 256
#define DD 768

// Scratch (no cudaMalloc allowed)
__device__ __half g_qh[BB*LQ*DD];        // q projection (fp16, feeds score)
__device__ __half g_kh[BB*LK*DD];        // k projection (fp16, feeds score)
__device__ __half g_vh[BB*LK*DD];        // v projection (fp16, feeds av)
__device__ __half g_xh[3][BB*LQ*DD];     // fp16 copies of query,key,value inputs
__device__ __half g_wh[3][DD*DD];        // fp16 copies of Wq,Wk,Wv
__device__ float  g_scores[BB*LQ*LK];

// ---- f16x2 helpers ----
__device__ __forceinline__ uint32_t hadd2u(uint32_t a, uint32_t b) {
    uint32_t r;
    asm("add.rn.f16x2 %0, %1, %2;" : "=r"(r) : "r"(a), "r"(b));
    return r;
}
__device__ __forceinline__ uint32_t tanh2u(uint32_t a) {
    uint32_t r;
    asm("tanh.approx.f16x2 %0, %1;" : "=r"(r) : "r"(a));
    return r;
}
__device__ __forceinline__ uint32_t hfma2u(uint32_t a, uint32_t b, uint32_t c) {
    uint32_t r;
    asm("fma.rn.f16x2 %0, %1, %2, %3;" : "=r"(r) : "r"(a), "r"(b), "r"(c));
    return r;
}
__device__ __forceinline__ float2 h22f2(uint32_t h) {
    __half2 hh = *(__half2*)&h;
    return __half22float2(hh);
}

// ---- fp16 mma helpers ----
__device__ __forceinline__ void mma_f16(float& d0, float& d1, float& d2, float& d3,
                                        uint32_t a0, uint32_t a1, uint32_t a2, uint32_t a3,
                                        uint32_t b0, uint32_t b1) {
    asm("mma.sync.aligned.m16n8k16.row.col.f32.f16.f16.f32 "
        "{%0,%1,%2,%3}, {%4,%5,%6,%7}, {%8,%9}, {%0,%1,%2,%3};"
        : "+f"(d0), "+f"(d1), "+f"(d2), "+f"(d3)
        : "r"(a0), "r"(a1), "r"(a2), "r"(a3), "r"(b0), "r"(b1));
}
__device__ __forceinline__ void ldsm_x4(uint32_t& r0, uint32_t& r1, uint32_t& r2, uint32_t& r3,
                                        uint32_t addr) {
    asm volatile("ldmatrix.sync.aligned.m8n8.x4.shared.b16 {%0,%1,%2,%3}, [%4];"
                 : "=r"(r0), "=r"(r1), "=r"(r2), "=r"(r3) : "r"(addr));
}
__device__ __forceinline__ void ldsm_x4_t(uint32_t& r0, uint32_t& r1, uint32_t& r2, uint32_t& r3,
                                          uint32_t addr) {
    asm volatile("ldmatrix.sync.aligned.m8n8.x4.trans.shared.b16 {%0,%1,%2,%3}, [%4];"
                 : "=r"(r0), "=r"(r1), "=r"(r2), "=r"(r3) : "r"(addr));
}

// ---------------------------------------------------------------------------
// Convert the 6 fp32 operand arrays to fp16 once. Grid (384, 6), 256 thr.
// ---------------------------------------------------------------------------
__global__ __launch_bounds__(256) void cvt_kernel(
    const float* __restrict__ xq, const float* __restrict__ xk, const float* __restrict__ xv,
    const float* __restrict__ Wq, const float* __restrict__ Wk, const float* __restrict__ Wv)
{
    const int id = blockIdx.y;
    const float* src;
    __half* dst;
    int n;
    if (id < 3) {
        src = (id == 0) ? xq : (id == 1) ? xk : xv;
        dst = g_xh[id];
        n = BB * LQ * DD;
    } else {
        src = (id == 3) ? Wq : (id == 4) ? Wk : Wv;
        dst = g_wh[id - 3];
        n = DD * DD;
    }
    const int idx = (blockIdx.x * 256 + threadIdx.x) * 8;
    if (idx >= n) return;
    float4 a = *(const float4*)(src + idx);
    float4 b = *(const float4*)(src + idx + 4);
    __half2 h0 = __floats2half2_rn(a.x, a.y);
    __half2 h1 = __floats2half2_rn(a.z, a.w);
    __half2 h2 = __floats2half2_rn(b.x, b.y);
    __half2 h3 = __floats2half2_rn(b.z, b.w);
    uint4 o;
    o.x = *(const uint32_t*)&h0;
    o.y = *(const uint32_t*)&h1;
    o.z = *(const uint32_t*)&h2;
    o.w = *(const uint32_t*)&h3;
    *(uint4*)(dst + idx) = o;
}

// ---------------------------------------------------------------------------
// Projection GEMM via fp16 mma (m16n8k16) + cp.async of pre-converted fp16.
// Out[M,N] = X[M,K]@W[K,N]+b, M=1024, N=K=768. 64x128 tile, 256 thr
// (2Mx4N warps, warp tile 32x32), BK=32 double-buffered. Grid (6,16,3).
// ALL outputs fp16 (q,k feed fp16 score; v feeds fp16 av).
// ---------------------------------------------------------------------------
__global__ __launch_bounds__(256) void proj_kernel(
    const float* __restrict__ bq, const float* __restrict__ bk, const float* __restrict__ bv)
{
    const int z = blockIdx.z;
    const __half* X = g_xh[z];
    const __half* W = g_wh[z];
    const float* bias = (z == 0) ? bq : (z == 1) ? bk : bv;
    __half* Out = (z == 0) ? g_qh : (z == 1) ? g_kh : g_vh;

    __shared__ __half As[2][64][40];
    __shared__ __half Bsm[2][32][136];

    const int t    = threadIdx.x;
    const int wid  = t >> 5;
    const int lane = t & 31;
    const int wm   = wid & 1;
    const int wn   = wid >> 1;
    const int grp  = lane >> 2;
    const int tig  = lane & 3;

    const int m0 = blockIdx.y * 64;
    const int n0 = blockIdx.x * 128;

    float acc[2][4][4];
    #pragma unroll
    for (int i = 0; i < 2; i++)
        #pragma unroll
        for (int j = 0; j < 4; j++)
            #pragma unroll
            for (int r = 0; r < 4; r++) acc[i][j][r] = 0.f;

    const int ar = t >> 2, acs = (t & 3) * 8;
    const int br = t >> 3, bcs = (t & 7) * 16;

    const __half* Xp = X + (size_t)(m0 + ar) * DD + acs;
    const __half* Wp = W + (size_t)br * DD + n0 + bcs;

    const int lrow = lane & 15;
    const int lca  = (lane >> 4) * 8;
    const uint32_t a_addr0 =
        (uint32_t)__cvta_generic_to_shared(&As[0][wm*32 + lrow][lca]);
    const int brow = ((lane >> 3) & 1) * 8 + (lane & 7);
    const int bcol = (lane >> 4) * 8;
    const uint32_t b_addr0 =
        (uint32_t)__cvta_generic_to_shared(&Bsm[0][brow][wn*32 + bcol]);

    __pipeline_memcpy_async(&As[0][ar][acs], Xp, 16);
    __pipeline_memcpy_async(&Bsm[0][br][bcs],     Wp,     16);
    __pipeline_memcpy_async(&Bsm[0][br][bcs + 8], Wp + 8, 16);
    __pipeline_commit();

    for (int k0 = 0; k0 < DD; k0 += 32) {
        const int buf = (k0 >> 5) & 1;
        if (k0 + 32 < DD) {
            const int nb = buf ^ 1;
            __pipeline_memcpy_async(&As[nb][ar][acs], Xp + k0 + 32, 16);
            const __half* wpn = Wp + (size_t)(k0 + 32) * DD;
            __pipeline_memcpy_async(&Bsm[nb][br][bcs],     wpn,     16);
            __pipeline_memcpy_async(&Bsm[nb][br][bcs + 8], wpn + 8, 16);
            __pipeline_commit();
            __pipeline_wait_prior(1);
        } else {
            __pipeline_wait_prior(0);
        }
        __syncthreads();

        #pragma unroll
        for (int ks = 0; ks < 2; ks++) {
            uint32_t a[2][4];
            #pragma unroll
            for (int mi = 0; mi < 2; mi++) {
                const uint32_t ad = a_addr0 + (uint32_t)(buf*5120 + mi*1280 + ks*32);
                ldsm_x4(a[mi][0], a[mi][1], a[mi][2], a[mi][3], ad);
            }
            uint32_t b[4][2];
            #pragma unroll
            for (int p = 0; p < 2; p++) {
                const uint32_t bd = b_addr0 + (uint32_t)(buf*8704 + ks*4352 + p*32);
                ldsm_x4_t(b[p*2][0], b[p*2][1], b[p*2+1][0], b[p*2+1][1], bd);
            }
            #pragma unroll
            for (int mi = 0; mi < 2; mi++)
                #pragma unroll
                for (int ni = 0; ni < 4; ni++)
                    mma_f16(acc[mi][ni][0], acc[mi][ni][1], acc[mi][ni][2], acc[mi][ni][3],
                            a[mi][0], a[mi][1], a[mi][2], a[mi][3],
                            b[ni][0], b[ni][1]);
        }
        __syncthreads();
    }

    #pragma unroll
    for (int mi = 0; mi < 2; mi++) {
        #pragma unroll
        for (int ni = 0; ni < 4; ni++) {
            const int col = n0 + wn*32 + ni*8 + 2*tig;
            const float b0 = bias[col], b1 = bias[col+1];
            const int r0 = m0 + wm*32 + mi*16 + grp;
            const int r1 = r0 + 8;
            __half2 lo = __floats2half2_rn(acc[mi][ni][0] + b0, acc[mi][ni][1] + b1);
            __half2 hi = __floats2half2_rn(acc[mi][ni][2] + b0, acc[mi][ni][3] + b1);
            *(__half2*)&Out[(size_t)r0 * DD + col] = lo;
            *(__half2*)&Out[(size_t)r1 * DD + col] = hi;
        }
    }
}

// ---------------------------------------------------------------------------
// Scores via tanh.approx.f16x2 (2x MUFU throughput):
// s = sum_d Ws[d]*tanh(q_d+k_d) + bs. 32x32 tile, 256 thr, 2x2 micro.
// fp16 HFMA2 partials over 4 d-pairs, flushed to fp32. Grid (8,8,4).
// ---------------------------------------------------------------------------
__global__ __launch_bounds__(256) void score_kernel(const float* __restrict__ Ws,
                                                    const float* __restrict__ bsp)
{
    const int bz = blockIdx.z;
    const int q0 = blockIdx.y * 32;
    const int k0 = blockIdx.x * 32;

    __shared__ uint32_t Qh[32][36];   // [qrow][dp] half2; pad 36 (16B-aligned rows)
    __shared__ uint32_t Kt[32][33];   // [dp][krow] half2 transposed; pad 33
    __shared__ uint32_t Wsh[32];      // Ws half2 pairs

    const int t  = threadIdx.x;
    const int tx = t & 15, ty = t >> 4;

    float acc00 = 0.f, acc01 = 0.f, acc10 = 0.f, acc11 = 0.f;

    const __half* qb = g_qh + ((size_t)bz*LQ + q0) * DD;
    const __half* kb = g_kh + ((size_t)bz*LK + k0) * DD;

    const int lr = t >> 3;          // 0..31
    const int lc = t & 7;           // 0..7  (8 halves = 4 half2 = 16B)

    for (int d0 = 0; d0 < DD; d0 += 64) {
        uint4 qv = *(const uint4*)(qb + (size_t)lr*DD + d0 + lc*8);
        *(uint4*)&Qh[lr][lc*4] = qv;
        uint4 kv = *(const uint4*)(kb + (size_t)lr*DD + d0 + lc*8);
        Kt[lc*4+0][lr] = kv.x;
        Kt[lc*4+1][lr] = kv.y;
        Kt[lc*4+2][lr] = kv.z;
        Kt[lc*4+3][lr] = kv.w;
        if (t < 32) {
            float2 w = *(const float2*)&Ws[d0 + t*2];
            __half2 wh = __floats2half2_rn(w.x, w.y);
            Wsh[t] = *(const uint32_t*)&wh;
        }
        __syncthreads();

        #pragma unroll
        for (int g = 0; g < 8; g++) {
            uint32_t p00 = 0u, p01 = 0u, p10 = 0u, p11 = 0u;   // fp16x2 partials
            #pragma unroll
            for (int u = 0; u < 4; u++) {
                const int dp = g*4 + u;
                const uint32_t w2  = Wsh[dp];
                const uint32_t qa  = Qh[ty*2+0][dp];
                const uint32_t qc  = Qh[ty*2+1][dp];
                const uint32_t ka  = Kt[dp][tx*2+0];
                const uint32_t kc  = Kt[dp][tx*2+1];
                p00 = hfma2u(w2, tanh2u(hadd2u(qa, ka)), p00);
                p01 = hfma2u(w2, tanh2u(hadd2u(qa, kc)), p01);
                p10 = hfma2u(w2, tanh2u(hadd2u(qc, ka)), p10);
                p11 = hfma2u(w2, tanh2u(hadd2u(qc, kc)), p11);
            }
            float2 f0 = h22f2(p00); acc00 += f0.x + f0.y;
            float2 f1 = h22f2(p01); acc01 += f1.x + f1.y;
            float2 f2 = h22f2(p10); acc10 += f2.x + f2.y;
            float2 f3 = h22f2(p11); acc11 += f3.x + f3.y;
        }
        __syncthreads();
    }

    const float bsv = *bsp;
    float* sp = g_scores + ((size_t)bz*LQ + q0) * LK + k0;
    sp[(ty*2+0)*LK + tx*2+0] = acc00 + bsv;
    sp[(ty*2+0)*LK + tx*2+1] = acc01 + bsv;
    sp[(ty*2+1)*LK + tx*2+0] = acc10 + bsv;
    sp[(ty*2+1)*LK + tx*2+1] = acc11 + bsv;
}

// ---------------------------------------------------------------------------
// Row softmax over LK=256. One block (256 threads) per (b,q) row.
// ---------------------------------------------------------------------------
__global__ __launch_bounds__(256) void softmax_kernel(float* __restrict__ wout)
{
    const int row = blockIdx.x;
    const int t   = threadIdx.x;
    __shared__ float red[8];

    const float v = g_scores[(size_t)row*LK + t];

    float m = v;
    #pragma unroll
    for (int o = 16; o > 0; o >>= 1) m = fmaxf(m, __shfl_xor_sync(0xffffffffu, m, o));
    if ((t & 31) == 0) red[t >> 5] = m;
    __syncthreads();
    float mx = red[0];
    #pragma unroll
    for (int i = 1; i < 8; i++) mx = fmaxf(mx, red[i]);
    __syncthreads();

    const float e = __expf(v - mx);
    float s = e;
    #pragma unroll
    for (int o = 16; o > 0; o >>= 1) s += __shfl_xor_sync(0xffffffffu, s, o);
    if ((t & 31) == 0) red[t >> 5] = s;
    __syncthreads();
    float sum = 0.f;
    #pragma unroll
    for (int i = 0; i < 8; i++) sum += red[i];

    wout[(size_t)row*LK + t] = e * (1.0f / sum);
}

// ---------------------------------------------------------------------------
// attended = weights @ v via fp16 mma. Tile 32q x 128d, 256 thr (8 warps:
// 1M x 8N, warp tile 32x16), BK=32 double-buffered. Grid (6,8,4).
// ---------------------------------------------------------------------------
__global__ __launch_bounds__(256) void av_kernel(const float* __restrict__ wts,
                                                 float* __restrict__ out)
{
    const int b  = blockIdx.z;
    const int q0 = blockIdx.y * 32;
    const int d0 = blockIdx.x * 128;

    __shared__ __half As[2][32][40];
    __shared__ __half Bsm[2][32][136];

    const int t    = threadIdx.x;
    const int wid  = t >> 5;
    const int lane = t & 31;
    const int grp  = lane >> 2;
    const int tig  = lane & 3;

    float acc[2][2][4];
    #pragma unroll
    for (int i = 0; i < 2; i++)
        #pragma unroll
        for (int j = 0; j < 2; j++)
            #pragma unroll
            for (int r = 0; r < 4; r++) acc[i][j][r] = 0.f;

    const int ar = t >> 3, ac4 = (t & 7) * 4;
    const int br = t >> 3, bcs = (t & 7) * 16;

    const float*  Ap = wts + ((size_t)b*LQ + q0 + ar) * LK + ac4;
    const __half* Bp = g_vh + ((size_t)b*LK + br) * DD + d0 + bcs;

    const int lrow = lane & 15;
    const int lca  = (lane >> 4) * 8;
    const uint32_t a_addr0 = (uint32_t)__cvta_generic_to_shared(&As[0][lrow][lca]);
    const int brow = ((lane >> 3) & 1) * 8 + (lane & 7);
    const int bcol = (lane >> 4) * 8;
    const uint32_t b_addr0 =
        (uint32_t)__cvta_generic_to_shared(&Bsm[0][brow][wid*16 + bcol]);

    float4 pa = *(const float4*)(Ap);
    __pipeline_memcpy_async(&Bsm[0][br][bcs],     Bp,     16);
    __pipeline_memcpy_async(&Bsm[0][br][bcs + 8], Bp + 8, 16);
    __pipeline_commit();

    for (int j0 = 0; j0 < LK; j0 += 32) {
        const int buf = (j0 >> 5) & 1;
        {
            __half2 h0 = __floats2half2_rn(pa.x, pa.y);
            __half2 h1 = __floats2half2_rn(pa.z, pa.w);
            uint2 o = { *(const uint32_t*)&h0, *(const uint32_t*)&h1 };
            *(uint2*)&As[buf][ar][ac4] = o;
        }
        if (j0 + 32 < LK) {
            const int nb = buf ^ 1;
            pa = *(const float4*)(Ap + j0 + 32);
            const __half* bpn = Bp + (size_t)(j0 + 32) * DD;
            __pipeline_memcpy_async(&Bsm[nb][br][bcs],     bpn,     16);
            __pipeline_memcpy_async(&Bsm[nb][br][bcs + 8], bpn + 8, 16);
            __pipeline_commit();
            __pipeline_wait_prior(1);
        } else {
            __pipeline_wait_prior(0);
        }
        __syncthreads();

        #pragma unroll
        for (int ks = 0; ks < 2; ks++) {
            uint32_t a[2][4];
            #pragma unroll
            for (int mi = 0; mi < 2; mi++) {
                const uint32_t ad = a_addr0 + (uint32_t)(buf*2560 + mi*1280 + ks*32);
                ldsm_x4(a[mi][0], a[mi][1], a[mi][2], a[mi][3], ad);
            }
            uint32_t bf[2][2];
            {
                const uint32_t bd = b_addr0 + (uint32_t)(buf*8704 + ks*4352);
                ldsm_x4_t(bf[0][0], bf[0][1], bf[1][0], bf[1][1], bd);
            }
            #pragma unroll
            for (int mi = 0; mi < 2; mi++)
                #pragma unroll
                for (int ni = 0; ni < 2; ni++)
                    mma_f16(acc[mi][ni][0], acc[mi][ni][1], acc[mi][ni][2], acc[mi][ni][3],
                            a[mi][0], a[mi][1], a[mi][2], a[mi][3],
                            bf[ni][0], bf[ni][1]);
        }
        __syncthreads();
    }

    #pragma unroll
    for (int mi = 0; mi < 2; mi++) {
        #pragma unroll
        for (int ni = 0; ni < 2; ni++) {
            const int col = d0 + wid*16 + ni*8 + 2*tig;
            const int r0  = q0 + mi*16 + grp;
            const int r1  = r0 + 8;
            float2 lo = { acc[mi][ni][0], acc[mi][ni][1] };
            float2 hi = { acc[mi][ni][2], acc[mi][ni][3] };
            *(float2*)&out[((size_t)b*LQ + r0) * DD + col] = lo;
            *(float2*)&out[((size_t)b*LQ + r1) * DD + col] = hi;
        }
    }
}

// ---------------------------------------------------------------------------
extern "C" void kernel_launch(void* const* d_in, const int* in_sizes, int n_in,
                              void* d_out, int out_size)
{
    const float* query = (const float*)d_in[0];
    const float* key   = (const float*)d_in[1];
    const float* value = (const float*)d_in[2];
    const float* Wq    = (const float*)d_in[3];
    const float* bq    = (const float*)d_in[4];
    const float* Wk    = (const float*)d_in[5];
    const float* bk    = (const float*)d_in[6];
    const float* Wv    = (const float*)d_in[7];
    const float* bv    = (const float*)d_in[8];
    const float* Ws    = (const float*)d_in[9];
    const float* bs    = (const float*)d_in[10];

    float* att = (float*)d_out;                  // [B,LQ,D]
    float* wts = att + (size_t)BB * LQ * DD;     // [B,LQ,LK]

    // 0) fp32 -> fp16 operand conversion (once)
    cvt_kernel<<<dim3(384, 6), 256>>>(query, key, value, Wq, Wk, Wv);

    // 1) q,k,v projections (fp16 mma; all outputs fp16)
    proj_kernel<<<dim3(DD/128, (BB*LQ)/64, 3), 256>>>(bq, bk, bv);

    // 2) additive scores (tanh.approx.f16x2, 2x MUFU rate)
    score_kernel<<<dim3(LK/32, LQ/32, BB), 256>>>(Ws, bs);

    // 3) softmax -> attention_weights into d_out
    softmax_kernel<<<BB*LQ, 256>>>(wts);

    // 4) attended = weights @ v (fp16 mma)
    av_kernel<<<dim3(DD/128, LQ/32, BB), 256>>>(wts, att);
}